// round 1
// baseline (speedup 1.0000x reference)
#include <cuda_runtime.h>
#include <math.h>

#define NW 1e-5f
#define CUTOFF_F 3.0f
#define SQRT2_F 1.41421356237309515f
#define INV_SQRT_PI_F 0.5641895835477563f

#define TPB 256
#define CHUNK 256      // m-values per block
#define MAX_PARAMS 65536
#define MAX_PARTIAL (1 << 21)

// Per-(b,m) precomputed params: {mu, c, k, pad}
__device__ float4 g_params[MAX_PARAMS];
// Partial sums: [num_chunks, B, N]
__device__ float g_partial[MAX_PARTIAL];

__global__ void precompute_kernel(const float* __restrict__ res_fields,
                                  const float* __restrict__ width,
                                  const float* __restrict__ A_mean,
                                  const float* __restrict__ area,
                                  const float* __restrict__ sf,
                                  int B, int M, int N) {
    int idx = blockIdx.x * blockDim.x + threadIdx.x;
    if (idx >= B * M) return;
    int b = idx / M;
    int m = idx - b * M;

    float r0 = res_fields[idx * 3 + 0];
    float r1 = res_fields[idx * 3 + 1];
    float r2 = res_fields[idx * 3 + 2];
    // sort descending (B1 >= B2 >= B3)
    float t;
    if (r0 < r1) { t = r0; r0 = r1; r1 = t; }
    if (r1 < r2) { t = r1; r1 = r2; r2 = t; }
    if (r0 < r1) { t = r0; r0 = r1; r1 = t; }

    float w = width[idx];
    w = (w > NW) ? w : w + NW;
    float d13 = (r0 - r2) / w;
    float d23 = (r1 - r2) / w;
    float d12 = (r0 - r1) / w;
    float add = (d13 * d13 + d23 * d23 + d12 * d12) * (1.0f / 9.0f);
    w = (w > 2.0f * NW) ? w : w + 2.0f * NW;

    float sw = (sf[b * N + 1] - sf[b * N]) * 0.5f;
    float ew = sqrtf(w * w * (1.0f + add) + sw * sw);
    ew = (ew < sw * 0.5f) ? ew : ew + sw * 0.5f;

    float mu = (r0 + r1 + r2) * (1.0f / 3.0f);
    float c = SQRT2_F / ew;
    float A = A_mean[idx] * area[m];
    float k = 2.0f * A * c * c * INV_SQRT_PI_F;

    g_params[idx] = make_float4(mu, c, k, 0.0f);
}

__global__ void spectra_main_kernel(const float* __restrict__ sf,
                                    int B, int M, int N) {
    __shared__ float4 sp[CHUNK];

    int b  = blockIdx.z;
    int mc = blockIdx.y;                 // m-chunk index
    int n  = blockIdx.x * TPB + threadIdx.x;

    int m0 = mc * CHUNK;
    int mcount = M - m0;
    if (mcount > CHUNK) mcount = CHUNK;

    // stage this chunk's params into shared memory (coalesced)
    const float4* gp = g_params + (size_t)b * M + m0;
    for (int i = threadIdx.x; i < CHUNK; i += TPB) {
        if (i < mcount) sp[i] = gp[i];
        else            sp[i] = make_float4(0.0f, 0.0f, 0.0f, 0.0f); // k=0 -> no contribution
    }
    __syncthreads();

    if (n >= N) return;
    float f = sf[b * N + n];
    float acc = 0.0f;

#pragma unroll 8
    for (int j = 0; j < CHUNK; ++j) {
        float4 p = sp[j];                 // broadcast LDS.128 (same addr all lanes)
        float arg = (p.x - f) * p.y;
        if (fabsf(arg) <= CUTOFF_F) {
            float e = __expf(-arg * arg);
            acc += arg * e * p.z;
        }
    }

    // deterministic partial store: [mc, b, n]
    g_partial[((size_t)mc * B + b) * N + n] = acc;
}

__global__ void reduce_kernel(float* __restrict__ out,
                              int B, int N, int num_chunks) {
    int i = blockIdx.x * blockDim.x + threadIdx.x;   // i = b*N + n
    if (i >= B * N) return;
    float s = 0.0f;
    size_t stride = (size_t)B * N;
#pragma unroll 8
    for (int mc = 0; mc < num_chunks; ++mc) {
        s += g_partial[(size_t)mc * stride + i];
    }
    out[i] = s;
}

extern "C" void kernel_launch(void* const* d_in, const int* in_sizes, int n_in,
                              void* d_out, int out_size) {
    const float* res_fields = (const float*)d_in[0];   // [B, M, 3]
    const float* width      = (const float*)d_in[1];   // [B, M]
    const float* A_mean     = (const float*)d_in[2];   // [B, M]
    const float* area       = (const float*)d_in[3];   // [M]
    const float* sf         = (const float*)d_in[4];   // [B, N]
    float* out = (float*)d_out;                        // [B, N]

    int M = in_sizes[3];
    int B = in_sizes[1] / M;
    int N = in_sizes[4] / B;

    int BM = B * M;
    int num_chunks = (M + CHUNK - 1) / CHUNK;

    precompute_kernel<<<(BM + TPB - 1) / TPB, TPB>>>(
        res_fields, width, A_mean, area, sf, B, M, N);

    dim3 grid((N + TPB - 1) / TPB, num_chunks, B);
    spectra_main_kernel<<<grid, TPB>>>(sf, B, M, N);

    int BN = B * N;
    reduce_kernel<<<(BN + TPB - 1) / TPB, TPB>>>(out, B, N, num_chunks);
}

// round 2
// speedup vs baseline: 1.2656x; 1.2656x over previous
#include <cuda_runtime.h>
#include <math.h>

#define NW 1e-5f
#define CUTOFF_F 3.0f
#define SQRT2_F 1.41421356237309515f
#define INV_SQRT_PI_F 0.5641895835477563f

#define TPB 256
#define CHUNK 256              // m-values per block (== TPB, one param per thread)
#define NWARPS (TPB / 32)
#define MAX_PARTIAL (1 << 21)

// Partial sums: [num_chunks, B, N]
__device__ float g_partial[MAX_PARTIAL];

__global__ void __launch_bounds__(TPB)
spectra_main_kernel(const float* __restrict__ res_fields,
                    const float* __restrict__ width,
                    const float* __restrict__ A_mean,
                    const float* __restrict__ area,
                    const float* __restrict__ sf,
                    int B, int M, int N) {
    __shared__ float4 sp[CHUNK];          // compacted params: {mu*c, c, k, pad}
    __shared__ int   s_warpcnt[NWARPS];
    __shared__ float s_flo, s_fhi;

    const int b  = blockIdx.z;
    const int mc = blockIdx.y;            // m-chunk index
    const int n  = blockIdx.x * TPB + threadIdx.x;
    const int lane = threadIdx.x & 31;
    const int wid  = threadIdx.x >> 5;

    // Block's field range (for window-intersection culling)
    if (threadIdx.x == 0) {
        int n0 = blockIdx.x * TPB;
        int n1 = n0 + TPB - 1; if (n1 >= N) n1 = N - 1;
        s_flo = sf[b * N + n0];
        s_fhi = sf[b * N + n1];
    }

    // Per-thread field value
    int n_clamped = (n < N) ? n : (N - 1);
    const float f = sf[b * N + n_clamped];

    __syncthreads();
    const float bc = 0.5f * (s_flo + s_fhi);
    const float hr = 0.5f * (s_fhi - s_flo);

    // ---- Fused param computation for m = mc*CHUNK + threadIdx.x ----
    const int m = mc * CHUNK + threadIdx.x;
    bool keep = false;
    float4 prm;
    if (m < M) {
        const int idx = b * M + m;
        float r0 = res_fields[idx * 3 + 0];
        float r1 = res_fields[idx * 3 + 1];
        float r2 = res_fields[idx * 3 + 2];
        float t;
        if (r0 < r1) { t = r0; r0 = r1; r1 = t; }
        if (r1 < r2) { t = r1; r1 = r2; r2 = t; }
        if (r0 < r1) { t = r0; r0 = r1; r1 = t; }

        float w = width[idx];
        w = (w > NW) ? w : w + NW;
        float invw = __fdividef(1.0f, w);
        float d13 = (r0 - r2) * invw;
        float d23 = (r1 - r2) * invw;
        float d12 = (r0 - r1) * invw;
        float add = (d13 * d13 + d23 * d23 + d12 * d12) * (1.0f / 9.0f);
        w = (w > 2.0f * NW) ? w : w + 2.0f * NW;

        // step/2 from this batch's grid (uniform grid)
        float sw = (s_fhi - s_flo) / (float)((blockDim.x - 1 > 0) ? (TPB - 1) : 1) * 0.5f;
        // NOTE: grid is uniform, so (fhi-flo)/(TPB-1) == step. But safer: recompute from sf:
        // (we already have only block-range; step = (fhi - flo)/(TPB-1)) — exact for uniform grid.

        float ew = sqrtf(w * w * (1.0f + add) + sw * sw);
        ew = (ew < sw * 0.5f) ? ew : ew + sw * 0.5f;

        float mu = (r0 + r1 + r2) * (1.0f / 3.0f);
        float c  = SQRT2_F / ew;
        float A  = A_mean[idx] * area[m];
        float k  = 2.0f * A * c * c * INV_SQRT_PI_F;

        // Window-intersection test: min over block n of |arg| <= CUTOFF
        float d = fabsf(mu - bc) - hr;
        if (d < 0.0f) d = 0.0f;
        keep = (d * c <= CUTOFF_F);

        prm = make_float4(mu * c, c, k, 0.0f);
    }

    // ---- Order-preserving compaction into shared ----
    unsigned bal = __ballot_sync(0xffffffffu, keep);
    if (lane == 0) s_warpcnt[wid] = __popc(bal);
    __syncthreads();

    int offset = __popc(bal & ((1u << lane) - 1u));
    int total = 0;
#pragma unroll
    for (int wi = 0; wi < NWARPS; ++wi) {
        int cnt = s_warpcnt[wi];
        if (wi < wid) offset += cnt;
        total += cnt;
    }
    if (keep) sp[offset] = prm;
    __syncthreads();

    // ---- Main accumulation over surviving m's ----
    float acc = 0.0f;
#pragma unroll 4
    for (int j = 0; j < total; ++j) {
        float4 p = sp[j];                           // broadcast LDS.128
        float arg = fmaf(-f, p.y, p.x);             // (mu - f) * c
        if (fabsf(arg) <= CUTOFF_F) {
            float e = __expf(-arg * arg);
            acc += arg * e * p.z;
        }
    }

    if (n < N)
        g_partial[((size_t)mc * B + b) * N + n] = acc;
}

__global__ void reduce_kernel(float* __restrict__ out,
                              int B, int N, int num_chunks) {
    int i = blockIdx.x * blockDim.x + threadIdx.x;   // i = b*N + n
    if (i >= B * N) return;
    float s = 0.0f;
    size_t stride = (size_t)B * N;
#pragma unroll 8
    for (int mcidx = 0; mcidx < num_chunks; ++mcidx) {
        s += g_partial[(size_t)mcidx * stride + i];
    }
    out[i] = s;
}

extern "C" void kernel_launch(void* const* d_in, const int* in_sizes, int n_in,
                              void* d_out, int out_size) {
    const float* res_fields = (const float*)d_in[0];   // [B, M, 3]
    const float* width      = (const float*)d_in[1];   // [B, M]
    const float* A_mean     = (const float*)d_in[2];   // [B, M]
    const float* area       = (const float*)d_in[3];   // [M]
    const float* sf         = (const float*)d_in[4];   // [B, N]
    float* out = (float*)d_out;                        // [B, N]

    int M = in_sizes[3];
    int B = in_sizes[1] / M;
    int N = in_sizes[4] / B;

    int num_chunks = (M + CHUNK - 1) / CHUNK;

    dim3 grid((N + TPB - 1) / TPB, num_chunks, B);
    spectra_main_kernel<<<grid, TPB>>>(res_fields, width, A_mean, area, sf, B, M, N);

    int BN = B * N;
    reduce_kernel<<<(BN + TPB - 1) / TPB, TPB>>>(out, B, N, num_chunks);
}